// round 3
// baseline (speedup 1.0000x reference)
#include <cuda_runtime.h>
#include <cstdint>

// Problem dims
#define NS   512                 // B*S
#define DD   150
#define HH   64
#define GG   192                 // 3H
#define LTT  32
#define LCC  128
#define LSEQ 160                 // LTT + LCC
#define ROWS_T (NS*LTT)          // 16384
#define ROWS_ALL (NS*(LTT+LCC))  // 81920

// Scratch (device globals; no runtime alloc allowed)
__device__ float g_X [ROWS_ALL*DD];   // embed sums (layer0 input)
__device__ float g_xg[ROWS_ALL*GG];   // layer0 input projection
__device__ float g_A [ROWS_ALL*HH];
__device__ float g_B [ROWS_ALL*HH];

// ---------- f32x2 helpers ----------
__device__ __forceinline__ unsigned long long pk2(float a, float b){
    unsigned long long r; asm("mov.b64 %0,{%1,%2};" : "=l"(r) : "f"(a), "f"(b)); return r;
}
__device__ __forceinline__ void fma2(unsigned long long &acc, unsigned long long a, unsigned long long b){
    asm("fma.rn.f32x2 %0, %1, %2, %0;" : "+l"(acc) : "l"(a), "l"(b));
}
__device__ __forceinline__ float upk_sum(unsigned long long a){
    float x, y; asm("mov.b64 {%0,%1}, %2;" : "=f"(x), "=f"(y) : "l"(a)); return x + y;
}

__device__ __forceinline__ float sigmoidf_(float x){
    return __fdividef(1.f, 1.f + __expf(-x));
}
__device__ __forceinline__ float tanhf_(float x){
    float ax = fabsf(x);
    float e  = __expf(-2.f*ax);
    float t  = __fdividef(1.f - e, 1.f + e);
    return (x < 0.f) ? -t : t;
}

// ---------- 1) embedding-bag sums ----------
__global__ void embed_kernel(const int* __restrict__ titles,
                             const int* __restrict__ contents,
                             const float* __restrict__ emb)
{
    int idx = blockIdx.x*blockDim.x + threadIdx.x;
    if (idx >= ROWS_ALL*75) return;          // 75 float2 per row (D=150)
    int row = idx / 75;
    int dp  = idx - row*75;

    const int* ip; int stride;
    if (row < ROWS_T){ int n = row >> 5, t = row & 31;  ip = titles   + (n*6)*32  + t; stride = 32; }
    else             { int r = row - ROWS_T;
                       int n = r >> 7,   t = r & 127;   ip = contents + (n*6)*128 + t; stride = 128; }

    float ax = 0.f, ay = 0.f;
    #pragma unroll
    for (int i = 0; i < 6; i++){
        int ix = ip[i*stride];
        if (ix != 0){
            float2 v = *(const float2*)(emb + (size_t)ix*DD + 2*dp);
            ax += v.x; ay += v.y;
        }
    }
    *(float2*)(g_X + (size_t)row*DD + 2*dp) = make_float2(ax, ay);
}

// ---------- 2) layer-0 input projection GEMM (K=150) ----------
__global__ void __launch_bounds__(256) xg_gemm150(const float* __restrict__ W,
                                                  const float* __restrict__ bias)
{
    __shared__ float sw[30*194];
    __shared__ float sx[64*32];
    int tid = threadIdx.x;
    int tx = tid & 31, ty = tid >> 5;
    int r0 = blockIdx.x * 64;

    unsigned long long acc[8][3];
    #pragma unroll
    for (int r = 0; r < 8; r++)
        #pragma unroll
        for (int c = 0; c < 3; c++) acc[r][c] = 0ull;

    for (int k0 = 0; k0 < 150; k0 += 30){
        for (int i = tid; i < 30*192; i += 256){
            int gg = i/30, kk = i - gg*30;
            sw[kk*194 + gg] = W[gg*150 + k0 + kk];
        }
        for (int i = tid; i < 64*30; i += 256){
            int rr = i/30, kk = i - rr*30;
            sx[rr*32 + kk] = g_X[(size_t)(r0+rr)*150 + k0 + kk];
        }
        __syncthreads();
        #pragma unroll 6
        for (int kk = 0; kk < 30; kk++){
            unsigned long long w2[3];
            #pragma unroll
            for (int c = 0; c < 3; c++)
                w2[c] = *(const unsigned long long*)&sw[kk*194 + tx*6 + 2*c];
            #pragma unroll
            for (int r = 0; r < 8; r++){
                float xv = sx[(ty*8 + r)*32 + kk];
                unsigned long long x2 = pk2(xv, xv);
                #pragma unroll
                for (int c = 0; c < 3; c++) fma2(acc[r][c], w2[c], x2);
            }
        }
        __syncthreads();
    }
    #pragma unroll
    for (int r = 0; r < 8; r++){
        int row = r0 + ty*8 + r;
        #pragma unroll
        for (int c = 0; c < 3; c++){
            float lo, hi;
            asm("mov.b64 {%0,%1}, %2;" : "=f"(lo), "=f"(hi) : "l"(acc[r][c]));
            int col = tx*6 + 2*c;
            float2 o; o.x = lo + bias[col]; o.y = hi + bias[col+1];
            *(float2*)(g_xg + (size_t)row*GG + col) = o;
        }
    }
}

// ---------- 3) batched GRU recurrence (distance-2 prefetch pipeline) ----------
// One CTA advances NSEQ sequences in lockstep; thread g owns gate row g.
// mode 0: info mid (X-layout in/out), mode 1: info final (X in, concat out),
// mode 2: comb (concat layout, T=160).
// Info grids: CONTENT blocks first (0..NS/NSEQ-1), then title blocks.
template<bool FUSED, int NSEQ>
__global__ void __launch_bounds__(192, 2) gru_rec(
    const float* __restrict__ xin,
    const float* __restrict__ Wih, const float* __restrict__ bih,
    const float* __restrict__ Whh, const float* __restrict__ bhh,
    float* __restrict__ yout, float* __restrict__ hid,
    int mode, int layer)
{
    __shared__ __align__(16) float sh_h[2][NSEQ][64];
    __shared__ __align__(16) float sh_x[2][NSEQ][64];
    __shared__ float sh_comb[NSEQ][192];
    __shared__ float sh_ghn[NSEQ][64];
    __shared__ int   sh_ob[NSEQ];

    const int b = blockIdx.x, g = threadIdx.x;
    int T, n0;
    int ibase[NSEQ];               // const-indexed only (stays in registers)

    if (mode == 2){
        n0 = b*NSEQ; T = LSEQ;
        #pragma unroll
        for (int s = 0; s < NSEQ; s++) ibase[s] = (n0+s)*LSEQ;
        if (g == 0){
            #pragma unroll
            for (int s = 0; s < NSEQ; s++) sh_ob[s] = ibase[s];
        }
    } else {
        const int nC = NS/NSEQ;    // content CTAs come first
        if (b < nC){
            n0 = b*NSEQ; T = LCC;
            #pragma unroll
            for (int s = 0; s < NSEQ; s++) ibase[s] = ROWS_T + (n0+s)*LCC;
            if (g == 0){
                #pragma unroll
                for (int s = 0; s < NSEQ; s++)
                    sh_ob[s] = (mode == 1) ? (n0+s)*LSEQ + LTT : ibase[s];
            }
        } else {
            n0 = (b-nC)*NSEQ; T = LTT;
            #pragma unroll
            for (int s = 0; s < NSEQ; s++) ibase[s] = (n0+s)*LTT;
            if (g == 0){
                #pragma unroll
                for (int s = 0; s < NSEQ; s++)
                    sh_ob[s] = (mode == 1) ? (n0+s)*LSEQ : ibase[s];
            }
        }
    }

    // Whh row g -> registers (32 x f32x2)
    unsigned long long wh[32];
    {   const float2* p = (const float2*)(Whh + g*HH);
        #pragma unroll
        for (int j = 0; j < 32; j++){ float2 v = __ldg(p + j); wh[j] = pk2(v.x, v.y); }
    }
    unsigned long long wx[FUSED ? 32 : 1];
    float bx = 0.f;
    if (FUSED){
        const float2* p = (const float2*)(Wih + g*HH);
        #pragma unroll
        for (int j = 0; j < 32; j++){ float2 v = __ldg(p + j); wx[j] = pk2(v.x, v.y); }
        bx = bih[g];
    }
    const float bh = bhh[g];

    if (g < 64){
        #pragma unroll
        for (int s = 0; s < NSEQ; s++) sh_h[0][s][g] = 0.f;
    }

    // x pipeline priming
    float xr[FUSED ? NSEQ : 1];            // register stage: holds x(t+1) (fused)
    float axc[FUSED ? 1 : NSEQ];           // current xg(t) (non-fused)
    if (FUSED){
        if (g >= 128){
            const int lane = g - 128;
            #pragma unroll
            for (int s = 0; s < NSEQ; s++){
                sh_x[0][s][lane] = __ldg(xin + (size_t)ibase[s]*HH + lane);
                xr[s] = (T > 1) ? __ldg(xin + (size_t)(ibase[s]+1)*HH + lane) : 0.f;
            }
        }
    } else {
        #pragma unroll
        for (int s = 0; s < NSEQ; s++)
            axc[s] = __ldg(xin + (size_t)ibase[s]*GG + g);
    }
    __syncthreads();

    int p = 0;
    for (int t = 0; t < T; t++){
        // ---- phase 1 ----
        float axn[FUSED ? 1 : NSEQ];       // prefetch xg(t+1) (non-fused)
        if (!FUSED){
            #pragma unroll
            for (int s = 0; s < NSEQ; s++)
                axn[s] = (t+1 < T) ? __ldg(xin + (size_t)(ibase[s]+t+1)*GG + g) : 0.f;
        }

        unsigned long long accH[NSEQ], accH2[FUSED ? 1 : NSEQ];
        unsigned long long accX[FUSED ? NSEQ : 1];
        #pragma unroll
        for (int s = 0; s < NSEQ; s++){
            accH[s] = 0ull;
            if (FUSED) accX[s] = 0ull; else accH2[s] = 0ull;
        }

        #pragma unroll
        for (int j = 0; j < 16; j++){
            #pragma unroll
            for (int s = 0; s < NSEQ; s++){
                ulonglong2 h4 = ((const ulonglong2*)sh_h[p][s])[j];
                if (FUSED){
                    ulonglong2 x4 = ((const ulonglong2*)sh_x[p][s])[j];
                    fma2(accH[s], wh[2*j],   h4.x);
                    fma2(accH[s], wh[2*j+1], h4.y);
                    fma2(accX[s], wx[2*j],   x4.x);
                    fma2(accX[s], wx[2*j+1], x4.y);
                } else {
                    fma2(accH[s],  wh[2*j],   h4.x);
                    fma2(accH2[s], wh[2*j+1], h4.y);
                }
            }
        }
        #pragma unroll
        for (int s = 0; s < NSEQ; s++){
            float ah = FUSED ? (bh + upk_sum(accH[s]))
                             : (bh + upk_sum(accH[s]) + upk_sum(accH2[s]));
            float ax = FUSED ? (bx + upk_sum(accX[s])) : axc[s];
            if (g < 128) sh_comb[s][g] = ax + ah;
            else { sh_comb[s][g] = ax; sh_ghn[s][g-128] = ah; }
        }
        __syncthreads();

        // ---- phase 2: gates on threads 0..127; x pipeline on 128..191 ----
        if (g < 128){
            #pragma unroll
            for (int q = 0; q < (NSEQ*64)/128; q++){
                int pp = g + q*128;
                int s = pp >> 6, i = pp & 63;
                float r  = sigmoidf_(sh_comb[s][i]);
                float z  = sigmoidf_(sh_comb[s][64 + i]);
                float nn = tanhf_(sh_comb[s][128 + i] + r*sh_ghn[s][i]);
                float h  = z*(sh_h[p][s][i] - nn) + nn;
                sh_h[p^1][s][i] = h;
                yout[(size_t)(sh_ob[s] + t)*HH + i] = h;
            }
        } else if (FUSED){
            const int lane = g - 128;
            if (t+1 < T){
                #pragma unroll
                for (int s = 0; s < NSEQ; s++) sh_x[p^1][s][lane] = xr[s];
            }
            if (t+2 < T){
                #pragma unroll
                for (int s = 0; s < NSEQ; s++)
                    xr[s] = __ldg(xin + (size_t)(ibase[s]+t+2)*HH + lane);
            }
        }
        __syncthreads();
        if (!FUSED){
            #pragma unroll
            for (int s = 0; s < NSEQ; s++) axc[s] = axn[s];
        }
        p ^= 1;
    }

    if (hid != nullptr && g < 64){
        #pragma unroll
        for (int s = 0; s < NSEQ; s++){
            int n = n0 + s;
            int bi = n >> 6, sidx = n & 63;
            hid[(size_t)(((bi*4 + layer)*64 + sidx)*64) + g] = sh_h[p][s][g];
        }
    }
}

// ---------- 4) prices passthrough ----------
__global__ void tail_kernel(const float* __restrict__ prices, float* __restrict__ out){
    int i = threadIdx.x;
    if (i < 512) out[i] = prices[i];
}

extern "C" void kernel_launch(void* const* d_in, const int* in_sizes, int n_in,
                              void* d_out, int out_size)
{
    const int*   titles   = (const int*)  d_in[0];
    const int*   contents = (const int*)  d_in[1];
    const float* prices   = (const float*)d_in[2];
    const float* emb      = (const float*)d_in[3];
    const float* iWih0    = (const float*)d_in[4];
    const float* iWhh0    = (const float*)d_in[5];
    const float* ibih0    = (const float*)d_in[6];
    const float* ibhh0    = (const float*)d_in[7];
    const float* iWih     = (const float*)d_in[8];   // [3][192][64]
    const float* iWhh     = (const float*)d_in[9];
    const float* ibih     = (const float*)d_in[10];  // [3][192]
    const float* ibhh     = (const float*)d_in[11];
    const float* cWih     = (const float*)d_in[12];  // [4][192][64]
    const float* cWhh     = (const float*)d_in[13];
    const float* cbih     = (const float*)d_in[14];
    const float* cbhh     = (const float*)d_in[15];

    float* out = (float*)d_out;
    float* hid = out + (size_t)8*64*160*64;          // encoder_hidden region
    float* pr  = hid + (size_t)8*4*64*64;            // prices region

    float *pXG = nullptr, *pA = nullptr, *pB = nullptr;
    cudaGetSymbolAddress((void**)&pXG, g_xg);
    cudaGetSymbolAddress((void**)&pA,  g_A);
    cudaGetSymbolAddress((void**)&pB,  g_B);

    // 1) embedding bags
    embed_kernel<<<(ROWS_ALL*75 + 255)/256, 256>>>(titles, contents, emb);

    // 2) info layer 0: input projection GEMM (K=150) then batched recurrence
    xg_gemm150<<<ROWS_ALL/64, 256>>>(iWih0, ibih0);
    gru_rec<false,4><<<256, 192>>>(pXG, nullptr, nullptr, iWhh0, ibhh0, pA, nullptr, 0, 0);

    // info layers 1..3 (fused input projection, 4 seqs/CTA); layer 3 -> concat layout
    gru_rec<true,4><<<256, 192>>>(pA, iWih + 0*GG*HH, ibih + 0*GG,
                                  iWhh + 0*GG*HH, ibhh + 0*GG, pB, nullptr, 0, 0);
    gru_rec<true,4><<<256, 192>>>(pB, iWih + 1*GG*HH, ibih + 1*GG,
                                  iWhh + 1*GG*HH, ibhh + 1*GG, pA, nullptr, 0, 0);
    gru_rec<true,4><<<256, 192>>>(pA, iWih + 2*GG*HH, ibih + 2*GG,
                                  iWhh + 2*GG*HH, ibhh + 2*GG, pB, nullptr, 1, 0);

    // comb layers 0..3 (T=160, 4 seqs/CTA, grid 128); final layer -> encoder_outputs
    gru_rec<true,4><<<128, 192>>>(pB, cWih + 0*GG*HH, cbih + 0*GG,
                                  cWhh + 0*GG*HH, cbhh + 0*GG, pA,  hid, 2, 0);
    gru_rec<true,4><<<128, 192>>>(pA, cWih + 1*GG*HH, cbih + 1*GG,
                                  cWhh + 1*GG*HH, cbhh + 1*GG, pB,  hid, 2, 1);
    gru_rec<true,4><<<128, 192>>>(pB, cWih + 2*GG*HH, cbih + 2*GG,
                                  cWhh + 2*GG*HH, cbhh + 2*GG, pA,  hid, 2, 2);
    gru_rec<true,4><<<128, 192>>>(pA, cWih + 3*GG*HH, cbih + 3*GG,
                                  cWhh + 3*GG*HH, cbhh + 3*GG, out, hid, 2, 3);

    // prices passthrough
    tail_kernel<<<1, 512>>>(prices, pr);
}

// round 4
// speedup vs baseline: 1.2627x; 1.2627x over previous
#include <cuda_runtime.h>
#include <cstdint>

// Problem dims
#define NS   512                 // B*S
#define DD   150
#define HH   64
#define GG   192                 // 3H
#define LTT  32
#define LCC  128
#define LSEQ 160                 // LTT + LCC
#define ROWS_T (NS*LTT)          // 16384
#define ROWS_ALL (NS*(LTT+LCC))  // 81920

// Scratch (device globals; no runtime alloc allowed)
__device__ float g_X [ROWS_ALL*DD];   // embed sums (layer0 input)
__device__ float g_xg[ROWS_ALL*GG];   // layer0 input projection
__device__ float g_A [ROWS_ALL*HH];
__device__ float g_B [ROWS_ALL*HH];

// ---------- f32x2 helpers ----------
__device__ __forceinline__ unsigned long long pk2(float a, float b){
    unsigned long long r; asm("mov.b64 %0,{%1,%2};" : "=l"(r) : "f"(a), "f"(b)); return r;
}
__device__ __forceinline__ void fma2(unsigned long long &acc, unsigned long long a, unsigned long long b){
    asm("fma.rn.f32x2 %0, %1, %2, %0;" : "+l"(acc) : "l"(a), "l"(b));
}
__device__ __forceinline__ float upk_sum(unsigned long long a){
    float x, y; asm("mov.b64 {%0,%1}, %2;" : "=f"(x), "=f"(y) : "l"(a)); return x + y;
}

__device__ __forceinline__ float sigmoidf_(float x){
    return __fdividef(1.f, 1.f + __expf(-x));
}
__device__ __forceinline__ float tanhf_(float x){
    float ax = fabsf(x);
    float e  = __expf(-2.f*ax);
    float t  = __fdividef(1.f - e, 1.f + e);
    return (x < 0.f) ? -t : t;
}

// ---------- 1) embedding-bag sums ----------
__global__ void embed_kernel(const int* __restrict__ titles,
                             const int* __restrict__ contents,
                             const float* __restrict__ emb)
{
    int idx = blockIdx.x*blockDim.x + threadIdx.x;
    if (idx >= ROWS_ALL*75) return;          // 75 float2 per row (D=150)
    int row = idx / 75;
    int dp  = idx - row*75;

    const int* ip; int stride;
    if (row < ROWS_T){ int n = row >> 5, t = row & 31;  ip = titles   + (n*6)*32  + t; stride = 32; }
    else             { int r = row - ROWS_T;
                       int n = r >> 7,   t = r & 127;   ip = contents + (n*6)*128 + t; stride = 128; }

    float ax = 0.f, ay = 0.f;
    #pragma unroll
    for (int i = 0; i < 6; i++){
        int ix = ip[i*stride];
        if (ix != 0){
            float2 v = *(const float2*)(emb + (size_t)ix*DD + 2*dp);
            ax += v.x; ay += v.y;
        }
    }
    *(float2*)(g_X + (size_t)row*DD + 2*dp) = make_float2(ax, ay);
}

// ---------- 2) layer-0 input projection GEMM (K=150) ----------
__global__ void __launch_bounds__(256) xg_gemm150(const float* __restrict__ W,
                                                  const float* __restrict__ bias)
{
    __shared__ float sw[30*194];
    __shared__ float sx[64*32];
    int tid = threadIdx.x;
    int tx = tid & 31, ty = tid >> 5;
    int r0 = blockIdx.x * 64;

    unsigned long long acc[8][3];
    #pragma unroll
    for (int r = 0; r < 8; r++)
        #pragma unroll
        for (int c = 0; c < 3; c++) acc[r][c] = 0ull;

    for (int k0 = 0; k0 < 150; k0 += 30){
        for (int i = tid; i < 30*192; i += 256){
            int gg = i/30, kk = i - gg*30;
            sw[kk*194 + gg] = W[gg*150 + k0 + kk];
        }
        for (int i = tid; i < 64*30; i += 256){
            int rr = i/30, kk = i - rr*30;
            sx[rr*32 + kk] = g_X[(size_t)(r0+rr)*150 + k0 + kk];
        }
        __syncthreads();
        #pragma unroll 6
        for (int kk = 0; kk < 30; kk++){
            unsigned long long w2[3];
            #pragma unroll
            for (int c = 0; c < 3; c++)
                w2[c] = *(const unsigned long long*)&sw[kk*194 + tx*6 + 2*c];
            #pragma unroll
            for (int r = 0; r < 8; r++){
                float xv = sx[(ty*8 + r)*32 + kk];
                unsigned long long x2 = pk2(xv, xv);
                #pragma unroll
                for (int c = 0; c < 3; c++) fma2(acc[r][c], w2[c], x2);
            }
        }
        __syncthreads();
    }
    #pragma unroll
    for (int r = 0; r < 8; r++){
        int row = r0 + ty*8 + r;
        #pragma unroll
        for (int c = 0; c < 3; c++){
            float lo, hi;
            asm("mov.b64 {%0,%1}, %2;" : "=f"(lo), "=f"(hi) : "l"(acc[r][c]));
            int col = tx*6 + 2*c;
            float2 o; o.x = lo + bias[col]; o.y = hi + bias[col+1];
            *(float2*)(g_xg + (size_t)row*GG + col) = o;
        }
    }
}

// ---------- 3) batched GRU recurrence, balanced two-phase step ----------
// Phase 1: h-matvec (all threads) + r/z sigmoids; threads>=128 also stage x(t+1).
// Phase 2: x-matvec for t+1 (all threads, FUSED) + tanh/update spread over all.
// mode 0: info mid (X-layout in/out), mode 1: info final (X in, concat out),
// mode 2: comb (concat layout, T=160). Info grids: content blocks first.
template<bool FUSED, int NSEQ>
__global__ void __launch_bounds__(192, 2) gru_rec(
    const float* __restrict__ xin,
    const float* __restrict__ Wih, const float* __restrict__ bih,
    const float* __restrict__ Whh, const float* __restrict__ bhh,
    float* __restrict__ yout, float* __restrict__ hid,
    int mode, int layer)
{
    __shared__ __align__(16) float sh_h[NSEQ][64];
    __shared__ __align__(16) float sh_x[FUSED ? NSEQ : 1][64];
    __shared__ float sh_r [NSEQ][64];
    __shared__ float sh_z [NSEQ][64];
    __shared__ float sh_an[NSEQ][64];
    __shared__ float sh_hn[NSEQ][64];
    __shared__ int   sh_ob[NSEQ];

    const int b = blockIdx.x, g = threadIdx.x;
    int T, n0;
    int ibase[NSEQ];               // const-indexed only (stays in registers)

    if (mode == 2){
        n0 = b*NSEQ; T = LSEQ;
        #pragma unroll
        for (int s = 0; s < NSEQ; s++) ibase[s] = (n0+s)*LSEQ;
        if (g == 0){
            #pragma unroll
            for (int s = 0; s < NSEQ; s++) sh_ob[s] = ibase[s];
        }
    } else {
        const int nC = NS/NSEQ;    // content CTAs first
        if (b < nC){
            n0 = b*NSEQ; T = LCC;
            #pragma unroll
            for (int s = 0; s < NSEQ; s++) ibase[s] = ROWS_T + (n0+s)*LCC;
            if (g == 0){
                #pragma unroll
                for (int s = 0; s < NSEQ; s++)
                    sh_ob[s] = (mode == 1) ? (n0+s)*LSEQ + LTT : ibase[s];
            }
        } else {
            n0 = (b-nC)*NSEQ; T = LTT;
            #pragma unroll
            for (int s = 0; s < NSEQ; s++) ibase[s] = (n0+s)*LTT;
            if (g == 0){
                #pragma unroll
                for (int s = 0; s < NSEQ; s++)
                    sh_ob[s] = (mode == 1) ? (n0+s)*LSEQ : ibase[s];
            }
        }
    }

    // Weight rows -> registers (f32x2)
    unsigned long long wh[32];
    {   const float2* p = (const float2*)(Whh + g*HH);
        #pragma unroll
        for (int j = 0; j < 32; j++){ float2 v = __ldg(p + j); wh[j] = pk2(v.x, v.y); }
    }
    unsigned long long wx[FUSED ? 32 : 1];
    float bx = 0.f;
    if (FUSED){
        const float2* p = (const float2*)(Wih + g*HH);
        #pragma unroll
        for (int j = 0; j < 32; j++){ float2 v = __ldg(p + j); wx[j] = pk2(v.x, v.y); }
        bx = bih[g];
    }
    const float bh = bhh[g];

    if (g < 64){
        #pragma unroll
        for (int s = 0; s < NSEQ; s++) sh_h[s][g] = 0.f;
    }

    float xacc[FUSED ? NSEQ : 1];      // x-matvec result for current step (FUSED)
    float xnext[FUSED ? NSEQ : 1];     // staged x(t+1) value (threads>=128)
    float axc[FUSED ? 1 : NSEQ];       // current xg(t) (non-fused)

    if (FUSED){
        if (g >= 128){
            const int lane = g - 128;
            #pragma unroll
            for (int s = 0; s < NSEQ; s++){
                sh_x[s][lane] = __ldg(xin + (size_t)ibase[s]*HH + lane);
                xnext[s] = (T > 1) ? __ldg(xin + (size_t)(ibase[s]+1)*HH + lane) : 0.f;
            }
        }
        __syncthreads();
        // prime xacc for t=0
        #pragma unroll
        for (int s = 0; s < NSEQ; s++){
            unsigned long long a = 0ull;
            #pragma unroll
            for (int j = 0; j < 16; j++){
                ulonglong2 x4 = ((const ulonglong2*)sh_x[s])[j];
                fma2(a, wx[2*j],   x4.x);
                fma2(a, wx[2*j+1], x4.y);
            }
            xacc[s] = upk_sum(a);
        }
        __syncthreads();   // protect sh_x from phase-1 overwrite racing prologue readers
    } else {
        #pragma unroll
        for (int s = 0; s < NSEQ; s++)
            axc[s] = __ldg(xin + (size_t)ibase[s]*GG + g);
        __syncthreads();
    }

    for (int t = 0; t < T; t++){
        // ================= phase 1: h-matvec + r/z sigmoids =================
        float axn[FUSED ? 1 : NSEQ];
        if (!FUSED){
            #pragma unroll
            for (int s = 0; s < NSEQ; s++)
                axn[s] = (t+1 < T) ? __ldg(xin + (size_t)(ibase[s]+t+1)*GG + g) : 0.f;
        }

        unsigned long long accH[NSEQ];
        #pragma unroll
        for (int s = 0; s < NSEQ; s++) accH[s] = 0ull;
        #pragma unroll
        for (int j = 0; j < 16; j++){
            #pragma unroll
            for (int s = 0; s < NSEQ; s++){
                ulonglong2 h4 = ((const ulonglong2*)sh_h[s])[j];
                fma2(accH[s], wh[2*j],   h4.x);
                fma2(accH[s], wh[2*j+1], h4.y);
            }
        }
        #pragma unroll
        for (int s = 0; s < NSEQ; s++){
            float ah = bh + upk_sum(accH[s]);
            float ax = FUSED ? (bx + xacc[s]) : axc[s];
            if (g < 64)        sh_r [s][g]       = sigmoidf_(ax + ah);
            else if (g < 128)  sh_z [s][g - 64]  = sigmoidf_(ax + ah);
            else             { sh_an[s][g - 128] = ax; sh_hn[s][g - 128] = ah; }
        }
        if (FUSED && g >= 128){
            const int lane = g - 128;
            if (t+1 < T){
                #pragma unroll
                for (int s = 0; s < NSEQ; s++) sh_x[s][lane] = xnext[s];
            }
            if (t+2 < T){
                #pragma unroll
                for (int s = 0; s < NSEQ; s++)
                    xnext[s] = __ldg(xin + (size_t)(ibase[s]+t+2)*HH + lane);
            }
        }
        __syncthreads();

        // ======== phase 2: x-matvec for t+1 (FUSED) + tanh/update ==========
        if (FUSED && (t+1) < T){
            #pragma unroll
            for (int s = 0; s < NSEQ; s++){
                unsigned long long a = 0ull;
                #pragma unroll
                for (int j = 0; j < 16; j++){
                    ulonglong2 x4 = ((const ulonglong2*)sh_x[s])[j];
                    fma2(a, wx[2*j],   x4.x);
                    fma2(a, wx[2*j+1], x4.y);
                }
                xacc[s] = upk_sum(a);
            }
        }
        #pragma unroll
        for (int q = 0; q < (NSEQ*64 + 191)/192; q++){
            int idx = g + q*192;
            if (idx < NSEQ*64){
                int s = idx >> 6, i = idx & 63;
                float r  = sh_r[s][i];
                float z  = sh_z[s][i];
                float nn = tanhf_(sh_an[s][i] + r*sh_hn[s][i]);
                float h  = z*(sh_h[s][i] - nn) + nn;
                sh_h[s][i] = h;
                yout[(size_t)(sh_ob[s] + t)*HH + i] = h;
            }
        }
        __syncthreads();
        if (!FUSED){
            #pragma unroll
            for (int s = 0; s < NSEQ; s++) axc[s] = axn[s];
        }
    }

    if (hid != nullptr && g < 64){
        #pragma unroll
        for (int s = 0; s < NSEQ; s++){
            int n = n0 + s;
            int bi = n >> 6, sidx = n & 63;
            hid[(size_t)(((bi*4 + layer)*64 + sidx)*64) + g] = sh_h[s][g];
        }
    }
}

// ---------- 4) prices passthrough ----------
__global__ void tail_kernel(const float* __restrict__ prices, float* __restrict__ out){
    int i = threadIdx.x;
    if (i < 512) out[i] = prices[i];
}

extern "C" void kernel_launch(void* const* d_in, const int* in_sizes, int n_in,
                              void* d_out, int out_size)
{
    const int*   titles   = (const int*)  d_in[0];
    const int*   contents = (const int*)  d_in[1];
    const float* prices   = (const float*)d_in[2];
    const float* emb      = (const float*)d_in[3];
    const float* iWih0    = (const float*)d_in[4];
    const float* iWhh0    = (const float*)d_in[5];
    const float* ibih0    = (const float*)d_in[6];
    const float* ibhh0    = (const float*)d_in[7];
    const float* iWih     = (const float*)d_in[8];   // [3][192][64]
    const float* iWhh     = (const float*)d_in[9];
    const float* ibih     = (const float*)d_in[10];  // [3][192]
    const float* ibhh     = (const float*)d_in[11];
    const float* cWih     = (const float*)d_in[12];  // [4][192][64]
    const float* cWhh     = (const float*)d_in[13];
    const float* cbih     = (const float*)d_in[14];
    const float* cbhh     = (const float*)d_in[15];

    float* out = (float*)d_out;
    float* hid = out + (size_t)8*64*160*64;          // encoder_hidden region
    float* pr  = hid + (size_t)8*4*64*64;            // prices region

    float *pXG = nullptr, *pA = nullptr, *pB = nullptr;
    cudaGetSymbolAddress((void**)&pXG, g_xg);
    cudaGetSymbolAddress((void**)&pA,  g_A);
    cudaGetSymbolAddress((void**)&pB,  g_B);

    // 1) embedding bags
    embed_kernel<<<(ROWS_ALL*75 + 255)/256, 256>>>(titles, contents, emb);

    // 2) info layer 0: input projection GEMM (K=150) then batched recurrence
    xg_gemm150<<<ROWS_ALL/64, 256>>>(iWih0, ibih0);
    gru_rec<false,8><<<128, 192>>>(pXG, nullptr, nullptr, iWhh0, ibhh0, pA, nullptr, 0, 0);

    // info layers 1..3 (fused input projection, 4 seqs/CTA); layer 3 -> concat layout
    gru_rec<true,4><<<256, 192>>>(pA, iWih + 0*GG*HH, ibih + 0*GG,
                                  iWhh + 0*GG*HH, ibhh + 0*GG, pB, nullptr, 0, 0);
    gru_rec<true,4><<<256, 192>>>(pB, iWih + 1*GG*HH, ibih + 1*GG,
                                  iWhh + 1*GG*HH, ibhh + 1*GG, pA, nullptr, 0, 0);
    gru_rec<true,4><<<256, 192>>>(pA, iWih + 2*GG*HH, ibih + 2*GG,
                                  iWhh + 2*GG*HH, ibhh + 2*GG, pB, nullptr, 1, 0);

    // comb layers 0..3 (T=160, 2 seqs/CTA, grid 256); final layer -> encoder_outputs
    gru_rec<true,2><<<256, 192>>>(pB, cWih + 0*GG*HH, cbih + 0*GG,
                                  cWhh + 0*GG*HH, cbhh + 0*GG, pA,  hid, 2, 0);
    gru_rec<true,2><<<256, 192>>>(pA, cWih + 1*GG*HH, cbih + 1*GG,
                                  cWhh + 1*GG*HH, cbhh + 1*GG, pB,  hid, 2, 1);
    gru_rec<true,2><<<256, 192>>>(pB, cWih + 2*GG*HH, cbih + 2*GG,
                                  cWhh + 2*GG*HH, cbhh + 2*GG, pA,  hid, 2, 2);
    gru_rec<true,2><<<256, 192>>>(pA, cWih + 3*GG*HH, cbih + 3*GG,
                                  cWhh + 3*GG*HH, cbhh + 3*GG, out, hid, 2, 3);

    // prices passthrough
    tail_kernel<<<1, 512>>>(prices, pr);
}